// round 1
// baseline (speedup 1.0000x reference)
#include <cuda_runtime.h>
#include <cuda_bf16.h>

// yolo_v3 detection head:
//   in : x [B, 255, 64, 64] f32, anchors [3,2] f32
//   out: [B, 4096*3, 85] f32
// out[b, (s*3+a)*85 + d] = f(x[b, a*85+d, s]) where
//   d==0: (sigmoid(v) + s%64) * 8
//   d==1: (sigmoid(v) + s/64) * 8
//   d==2,3: exp(v) * anchors[a][d-2]      (stride factors cancel)
//   d>=4: sigmoid(v)

#define S_DIM 64
#define WH    4096           // S*S
#define NA    3
#define ND    85
#define NC    255            // NA*ND
#define TS    32             // s-values per block
#define PITCH 33             // smem pitch (conflict-free)

__global__ __launch_bounds__(256)
void yolo_head_kernel(const float* __restrict__ x,
                      const float* __restrict__ anchors,
                      float* __restrict__ out)
{
    __shared__ float tile[NC * PITCH];   // 255*33*4 = 33660 B
    __shared__ float anc[NA * 2];

    const int s0  = blockIdx.x * TS;
    const int b   = blockIdx.y;
    const int tid = threadIdx.x;

    if (tid < NA * 2) anc[tid] = anchors[tid];

    // ---- Phase 1: coalesced vectorized load into smem transpose tile ----
    // x row for channel c starts at b*NC*WH + c*WH + s0; s0 % 32 == 0 so
    // float4 access is aligned. 255 channels * 8 float4 = 2040 loads.
    const float4* __restrict__ xin =
        reinterpret_cast<const float4*>(x + (size_t)b * NC * WH + s0);
    #pragma unroll 4
    for (int i = tid; i < NC * (TS / 4); i += 256) {
        int c = i >> 3;          // channel
        int q = i & 7;           // float4 index within the 32-wide row
        float4 v = xin[c * (WH / 4) + q];
        float* dst = &tile[c * PITCH + q * 4];
        dst[0] = v.x; dst[1] = v.y; dst[2] = v.z; dst[3] = v.w;
    }
    __syncthreads();

    // ---- Phase 2: contiguous output slab, transform per element ----
    // Output region for this block: 32 s-values * 255 = 8160 contiguous floats.
    float* __restrict__ outp = out + (size_t)b * WH * NC + (size_t)s0 * NC;
    #pragma unroll 4
    for (int i = tid; i < TS * NC; i += 256) {
        int sl = i / NC;             // local s (0..31)
        int r  = i - sl * NC;        // channel = a*85 + d
        int a  = r / ND;
        int d  = r - a * ND;
        float v = tile[r * PITCH + sl];
        float res;
        if (d >= 4) {
            res = __fdividef(1.0f, 1.0f + __expf(-v));
        } else if (d < 2) {
            int s = s0 + sl;
            float off = (d == 0) ? (float)(s & (S_DIM - 1))
                                 : (float)(s >> 6);
            res = (__fdividef(1.0f, 1.0f + __expf(-v)) + off) * 8.0f;
        } else {   // d == 2 or 3
            res = __expf(v) * anc[a * 2 + (d - 2)];
        }
        outp[i] = res;
    }
}

extern "C" void kernel_launch(void* const* d_in, const int* in_sizes, int n_in,
                              void* d_out, int out_size)
{
    const float* x       = (const float*)d_in[0];
    const float* anchors = (const float*)d_in[1];
    float* out           = (float*)d_out;

    int B = in_sizes[0] / (NC * WH);   // 32 for this problem
    dim3 grid(WH / TS, B);
    yolo_head_kernel<<<grid, 256>>>(x, anchors, out);
}

// round 2
// speedup vs baseline: 1.2740x; 1.2740x over previous
#include <cuda_runtime.h>
#include <cuda_bf16.h>

// yolo_v3 detection head:
//   in : x [B, 255, 64, 64] f32, anchors [3,2] f32
//   out: [B, 4096*3, 85] f32
// out[b, (s*3+a)*85 + d] = f(x[b, a*85+d, s]) where
//   d==0: (sigmoid(v) + s%64) * 8
//   d==1: (sigmoid(v) + s/64) * 8
//   d==2,3: exp(v) * anchors[a][d-2]      (stride factors cancel: 8/8)
//   d>=4: sigmoid(v)
//
// Unified branch-free form (one __expf serves sigmoid and exp):
//   e   = exp(v)
//   res = e * 1/(1 + e*ne) * scale + offbase + offstep*sl
//   ne=1,scale=8,off=x-grid   (d==0)
//   ne=1,scale=8,off=y-grid   (d==1)
//   ne=0,scale=anchor,off=0   (d==2,3)   [1/(1+0)=1 -> pure exp]
//   ne=1,scale=1,off=0        (d>=4)

#define S_DIM 64
#define WH    4096
#define NA    3
#define ND    85
#define NC    255
#define TS    32
#define PITCH 33

__global__ __launch_bounds__(256)
void yolo_head_kernel(const float* __restrict__ x,
                      const float* __restrict__ anchors,
                      float* __restrict__ out)
{
    __shared__ float tile[NC * PITCH];   // 255*33*4 = 33660 B

    const int s0  = blockIdx.x * TS;
    const int b   = blockIdx.y;
    const int tid = threadIdx.x;

    // ---- Phase 1: coalesced float4 load into smem transpose tile ----
    const float4* __restrict__ xin =
        reinterpret_cast<const float4*>(x + (size_t)b * NC * WH + s0);
    #pragma unroll 4
    for (int i = tid; i < NC * (TS / 4); i += 256) {
        int c = i >> 3;          // channel
        int q = i & 7;           // float4 within the 32-wide row
        float4 v = xin[c * (WH / 4) + q];
        float* dst = &tile[c * PITCH + q * 4];
        dst[0] = v.x; dst[1] = v.y; dst[2] = v.z; dst[3] = v.w;
    }

    // ---- Per-thread channel constants (computed while loads are in flight) ----
    // Thread tid owns channel r = tid (tid==255 idle in phase 2).
    const int r = tid;
    float ne = 1.0f, scale = 1.0f, offbase = 0.0f, offstep = 0.0f;
    if (r < NC) {
        int a = r / ND;
        int d = r - a * ND;
        float fxb = (float)((s0 & (S_DIM - 1)));  // 0 or 32, no carry: sl<32
        float fyb = (float)(s0 >> 6);             // constant within block
        if (d == 0)      { scale = 8.0f; offbase = 8.0f * fxb; offstep = 8.0f; }
        else if (d == 1) { scale = 8.0f; offbase = 8.0f * fyb; offstep = 0.0f; }
        else if (d < 4)  { ne = 0.0f; scale = __ldg(&anchors[a * 2 + (d - 2)]); }
        // d>=4: defaults (sigmoid)
    }

    __syncthreads();

    // ---- Phase 2: 32 s-values per thread, fixed channel, coalesced stores ----
    if (r < NC) {
        float* __restrict__ outp =
            out + (size_t)b * WH * NC + (size_t)s0 * NC + r;
        const float* __restrict__ trow = &tile[r * PITCH];
        #pragma unroll 8
        for (int sl = 0; sl < TS; sl++) {
            float v = trow[sl];                    // bank (r+sl)%32: conflict-free
            float e = __expf(v);
            float t = __fdividef(1.0f, fmaf(e, ne, 1.0f));
            float res = fmaf(e * t, scale, fmaf(offstep, (float)sl, offbase));
            outp[sl * NC] = res;
        }
    }
}

extern "C" void kernel_launch(void* const* d_in, const int* in_sizes, int n_in,
                              void* d_out, int out_size)
{
    const float* x       = (const float*)d_in[0];
    const float* anchors = (const float*)d_in[1];
    float* out           = (float*)d_out;

    int B = in_sizes[0] / (NC * WH);
    dim3 grid(WH / TS, B);
    yolo_head_kernel<<<grid, 256>>>(x, anchors, out);
}

// round 3
// speedup vs baseline: 1.4148x; 1.1105x over previous
#include <cuda_runtime.h>
#include <cuda_bf16.h>

// yolo_v3 detection head:
//   in : x [B, 255, 64, 64] f32, anchors [3,2] f32
//   out: [B, 4096*3, 85] f32
// out[b, (s*3+a)*85 + d] = f(x[b, a*85+d, s]) where
//   d==0: (sigmoid(v) + s%64) * 8
//   d==1: (sigmoid(v) + s/64) * 8
//   d==2,3: exp(v) * anchors[a][d-2]      (stride factors cancel: 8/8)
//   d>=4: sigmoid(v)
//
// Unified branch-free form (one __expf serves sigmoid and exp):
//   e   = exp(v)
//   res = e * 1/(1 + e*ne) * scale + offbase + offstep*sl

#define S_DIM 64
#define WH    4096
#define NA    3
#define ND    85
#define NC    255
#define TS    16             // s-values per block (16 -> 17.3KB smem, 8 blk/SM)
#define PITCH 17             // odd pitch: conflict-free stride access

__global__ __launch_bounds__(256)
void yolo_head_kernel(const float* __restrict__ x,
                      const float* __restrict__ anchors,
                      float* __restrict__ out)
{
    __shared__ float tile[NC * PITCH];   // 255*17*4 = 17340 B

    const int s0  = blockIdx.x * TS;
    const int b   = blockIdx.y;
    const int tid = threadIdx.x;

    // ---- Phase 1: coalesced float4 load into smem transpose tile ----
    // Each channel row: 16 floats = 4 float4 (64B, aligned since s0%16==0).
    const float4* __restrict__ xin =
        reinterpret_cast<const float4*>(x + (size_t)b * NC * WH + s0);
    #pragma unroll 4
    for (int i = tid; i < NC * (TS / 4); i += 256) {
        int c = i >> 2;          // channel
        int q = i & 3;           // float4 within the 16-wide row
        float4 v = xin[c * (WH / 4) + q];
        float* dst = &tile[c * PITCH + q * 4];
        dst[0] = v.x; dst[1] = v.y; dst[2] = v.z; dst[3] = v.w;
    }

    // ---- Per-thread channel constants (overlap with loads in flight) ----
    const int r = tid;           // thread owns channel r; tid==255 idle
    float ne = 1.0f, scale = 1.0f, offbase = 0.0f, offstep = 0.0f;
    if (r < NC) {
        int a = r / ND;
        int d = r - a * ND;
        float fxb = (float)(s0 & (S_DIM - 1));  // 0/16/32/48; sl<16 -> no carry
        float fyb = (float)(s0 >> 6);           // constant within block
        if (d == 0)      { scale = 8.0f; offbase = 8.0f * fxb; offstep = 8.0f; }
        else if (d == 1) { scale = 8.0f; offbase = 8.0f * fyb; offstep = 0.0f; }
        else if (d < 4)  { ne = 0.0f; scale = __ldg(&anchors[a * 2 + (d - 2)]); }
        // d>=4: defaults (pure sigmoid)
    }

    __syncthreads();

    // ---- Phase 2: 16 s-values per thread, fixed channel, coalesced stores ----
    if (r < NC) {
        float* __restrict__ outp =
            out + (size_t)b * WH * NC + (size_t)s0 * NC + r;
        const float* __restrict__ trow = &tile[r * PITCH];
        #pragma unroll 16
        for (int sl = 0; sl < TS; sl++) {
            float v = trow[sl];                 // bank (17r+sl)%32: conflict-free
            float e = __expf(v);
            float t = __fdividef(1.0f, fmaf(e, ne, 1.0f));
            float res = fmaf(e * t, scale, fmaf(offstep, (float)sl, offbase));
            outp[sl * NC] = res;
        }
    }
}

extern "C" void kernel_launch(void* const* d_in, const int* in_sizes, int n_in,
                              void* d_out, int out_size)
{
    const float* x       = (const float*)d_in[0];
    const float* anchors = (const float*)d_in[1];
    float* out           = (float*)d_out;

    int B = in_sizes[0] / (NC * WH);
    dim3 grid(WH / TS, B);
    yolo_head_kernel<<<grid, 256>>>(x, anchors, out);
}

// round 5
// speedup vs baseline: 1.5844x; 1.1199x over previous
#include <cuda_runtime.h>
#include <cuda_bf16.h>
#include <cstdint>

// yolo_v3 detection head:
//   in : x [B, 255, 64, 64] f32, anchors [3,2] f32
//   out: [B, 4096*3, 85] f32
// out[b, s*255 + r] = f(x[b, r, s]),  r = a*85+d:
//   d==0: (sigmoid(v) + s%64) * 8
//   d==1: (sigmoid(v) + s/64) * 8
//   d==2,3: exp(v) * anchors[a][d-2]   (stride factors cancel)
//   d>=4: sigmoid(v)
// Unified: e=exp(v); res = e * 1/(1+ne*e) * scale + off

#define S_DIM 64
#define WH    4096
#define NA    3
#define ND    85
#define NC    255
#define TS    16                    // s-values per block
#define TILE_BYTES (TS * NC * 4)    // 16320 B == output slab for this block

__global__ __launch_bounds__(256)
void yolo_head_kernel(const float* __restrict__ x,
                      const float* __restrict__ anchors,
                      float* __restrict__ out)
{
    __shared__ __align__(16) float tile[TS * NC];   // output-layout tile

    const int s0  = blockIdx.x * TS;
    const int b   = blockIdx.y;
    const int tid = threadIdx.x;

    const float fxb = (float)(s0 & (S_DIM - 1));    // s&63 base (no carry, TS=16)
    const float fyb = (float)(s0 >> 6);             // constant within block

    // ---- Phase 1: load float4 along s, transform, scatter into output-layout tile ----
    const float4* __restrict__ xin =
        reinterpret_cast<const float4*>(x + (size_t)b * NC * WH + s0);

    #pragma unroll
    for (int k = 0; k < 4; k++) {
        int i = tid + k * 256;
        if (i < NC * (TS / 4)) {            // 1020 (c,q) pairs
            int c = i >> 2;                 // channel 0..254
            int q = i & 3;                  // float4 index within 16-wide row
            float4 v = xin[c * (WH / 4) + q];

            // channel params, division-free (c < 255)
            int a = (c >= 2 * ND) ? 2 : (c >= ND ? 1 : 0);
            int d = c - a * ND;
            float ne = 1.0f, scale = 1.0f, offbase = 0.0f, offstep = 0.0f;
            if (d == 0)      { scale = 8.0f; offbase = 8.0f * (fxb + 4 * q); offstep = 8.0f; }
            else if (d == 1) { scale = 8.0f; offbase = 8.0f * fyb; }
            else if (d < 4)  { ne = 0.0f; scale = __ldg(&anchors[a * 2 + (d - 2)]); }

            float vv[4] = {v.x, v.y, v.z, v.w};
            float* dst = &tile[(q * 4) * NC + c];
            #pragma unroll
            for (int j = 0; j < 4; j++) {
                float e = __expf(vv[j]);
                float t = __fdividef(1.0f, fmaf(e, ne, 1.0f));
                dst[j * NC] = fmaf(e * t, scale, fmaf(offstep, (float)j, offbase));
            }
        }
    }

    __syncthreads();

    // ---- Phase 2: one bulk DMA copy smem -> gmem (tile layout == output slab) ----
    if (tid == 0) {
        asm volatile("fence.proxy.async.shared::cta;" ::: "memory");
        float* gdst = out + (size_t)b * WH * NC + (size_t)s0 * NC;
        uint32_t saddr;
        asm("{ .reg .u64 t; cvta.to.shared.u64 t, %1; cvt.u32.u64 %0, t; }"
            : "=r"(saddr) : "l"(tile));
        uint32_t nbytes = TILE_BYTES;
        asm volatile(
            "cp.async.bulk.global.shared::cta.bulk_group [%0], [%1], %2;"
            :: "l"(gdst), "r"(saddr), "r"(nbytes) : "memory");
        asm volatile("cp.async.bulk.commit_group;" ::: "memory");
        asm volatile("cp.async.bulk.wait_group 0;" ::: "memory");
    }
}

extern "C" void kernel_launch(void* const* d_in, const int* in_sizes, int n_in,
                              void* d_out, int out_size)
{
    const float* x       = (const float*)d_in[0];
    const float* anchors = (const float*)d_in[1];
    float* out           = (float*)d_out;

    int B = in_sizes[0] / (NC * WH);
    dim3 grid(WH / TS, B);
    yolo_head_kernel<<<grid, 256>>>(x, anchors, out);
}